// round 9
// baseline (speedup 1.0000x reference)
#include <cuda_runtime.h>
#include <cstdint>

#define Tt 1024
#define Bb 64
#define Ii 512
#define Hh 1024
#define Gg 3072
#define Oo 256
#define NCTA 128

// scratch (device globals = allowed scratch)
__device__ float g_gi[(size_t)Tt * Bb * Gg];        // [t][b][g]
__device__ float g_h [(size_t)(Tt + 1) * Hh * Bb];  // [t][k][b], slot 0 = init^T
__device__ unsigned g_bar_count;

typedef unsigned long long u64;

__device__ __forceinline__ u64 pk2(float x, float y) {
    u64 r; asm("mov.b64 %0,{%1,%2};" : "=l"(r) : "f"(x), "f"(y)); return r;
}
__device__ __forceinline__ void f2(u64& d, u64 a, u64 b) {
    asm("fma.rn.f32x2 %0,%1,%2,%0;" : "+l"(d) : "l"(a), "l"(b));
}
__device__ __forceinline__ u64 add2(u64 a, u64 b) {
    u64 d; asm("add.rn.f32x2 %0,%1,%2;" : "=l"(d) : "l"(a), "l"(b)); return d;
}
__device__ __forceinline__ float2 up2(u64 a) {
    float2 f; asm("mov.b64 {%0,%1},%2;" : "=f"(f.x), "=f"(f.y) : "l"(a)); return f;
}
__device__ __forceinline__ float sigm(float x) { return 1.0f / (1.0f + __expf(-x)); }

__device__ __forceinline__ void cp16(void* smem, const void* g) {
    uint32_t s = (uint32_t)__cvta_generic_to_shared(smem);
    asm volatile("cp.async.cg.shared.global [%0], [%1], 16;" :: "r"(s), "l"(g));
}

__global__ void init_bar() { g_bar_count = 0u; }

// transpose init [b][k] -> g_h slot 0 [k][b]
__global__ void h0_init(const float* __restrict__ init) {
    int i = blockIdx.x * 256 + threadIdx.x;   // 65536
    int k = i >> 6, b = i & 63;
    g_h[(size_t)k * Bb + b] = init[(size_t)b * Hh + k];
}

// ---------------------------------------------------------------------------
// SGEMM: C[M,N] = A[M,K] @ W[K,N] + bias.  BM=128, BN=64, BK=16, 256 threads,
// thread-tile 8m x 4n (n packed as f32x2 pairs).
// MODE 0: A=X [M=b*1024+t, K=512], W_ih ldw=3072, writes g_gi[t][b][g].
// MODE 1: A=g_h transposed [t][k][b] (m=t*64+b), K=1024, ldw=256, writes out.
// ---------------------------------------------------------------------------
template <int K, int MODE>
__global__ __launch_bounds__(256) void sgemm(const float* __restrict__ Ain,
                                             const float* __restrict__ W,
                                             const float* __restrict__ bias,
                                             float* __restrict__ Cout)
{
    __shared__ float As[16][132];
    __shared__ float Bs[16][64];
    const int ldw = (MODE == 0) ? Gg : Oo;
    const int m0 = blockIdx.y * 128, n0 = blockIdx.x * 64;
    const int tid = threadIdx.x;
    const int tn = tid & 15, tm = tid >> 4;

    u64 acc[8][2];
    #pragma unroll
    for (int m = 0; m < 8; m++) { acc[m][0] = 0ull; acc[m][1] = 0ull; }

    for (int k0 = 0; k0 < K; k0 += 16) {
        if (MODE == 0) {
            #pragma unroll
            for (int i = 0; i < 2; i++) {
                int idx = tid + i * 256;            // 512 float4 = 128 rows x 4
                int r = idx >> 2, kq = idx & 3;
                float4 v = *(const float4*)(Ain + (size_t)(m0 + r) * K + k0 + kq * 4);
                As[kq * 4 + 0][r] = v.x; As[kq * 4 + 1][r] = v.y;
                As[kq * 4 + 2][r] = v.z; As[kq * 4 + 3][r] = v.w;
            }
        } else {
            // tile = 2 t-slices x 16 k x 64 b from g_h[t+1][k][b]
            #pragma unroll
            for (int i = 0; i < 2; i++) {
                int idx = tid + i * 256;            // 512 float4
                int tsl = idx >> 8, k = (idx >> 4) & 15, q = idx & 15;
                float4 v = *(const float4*)(g_h +
                    (size_t)((m0 >> 6) + tsl + 1) * (Hh * Bb) + (size_t)(k0 + k) * Bb + q * 4);
                *(float4*)&As[k][tsl * 64 + q * 4] = v;
            }
        }
        {
            int r = tid >> 4, gq = tid & 15;        // 16 rows x 16 float4
            *(float4*)&Bs[r][gq * 4] =
                *(const float4*)(W + (size_t)(k0 + r) * ldw + n0 + gq * 4);
        }
        __syncthreads();
        #pragma unroll
        for (int k = 0; k < 16; k++) {
            float4 a0 = *(float4*)&As[k][tm * 8];
            float4 a1 = *(float4*)&As[k][tm * 8 + 4];
            u64 b0 = *(u64*)&Bs[k][tn * 4];
            u64 b1 = *(u64*)&Bs[k][tn * 4 + 2];
            float av[8] = {a0.x, a0.y, a0.z, a0.w, a1.x, a1.y, a1.z, a1.w};
            #pragma unroll
            for (int m = 0; m < 8; m++) {
                u64 ad = pk2(av[m], av[m]);
                f2(acc[m][0], ad, b0);
                f2(acc[m][1], ad, b1);
            }
        }
        __syncthreads();
    }

    const int n = n0 + tn * 4;
    float4 bi = *(const float4*)(bias + n);
    #pragma unroll
    for (int m = 0; m < 8; m++) {
        int r = m0 + tm * 8 + m;
        float2 p0 = up2(acc[m][0]), p1 = up2(acc[m][1]);
        float4 o = make_float4(p0.x + bi.x, p0.y + bi.y, p1.x + bi.z, p1.y + bi.w);
        if (MODE == 0) {
            int b = r >> 10, t = r & 1023;
            *(float4*)(g_gi + ((size_t)t * Bb + b) * Gg + n) = o;
        } else {
            int t = r >> 6, b = r & 63;
            *(float4*)(Cout + ((size_t)b * Tt + t) * Oo + n) = o;
        }
    }
}

// ---------------------------------------------------------------------------
// Grid barrier: monotonic arrival counter, target = (t+1)*NCTA.
// ---------------------------------------------------------------------------
__device__ __forceinline__ void grid_bar(unsigned t1) {
    __syncthreads();
    if (threadIdx.x == 0) {
        unsigned* pc = &g_bar_count;
        asm volatile("red.add.release.gpu.u32 [%0],1;" :: "l"(pc) : "memory");
        const unsigned target = t1 * NCTA;
        unsigned g;
        do {
            asm volatile("ld.acquire.gpu.u32 %0,[%1];" : "=r"(g) : "l"(pc) : "memory");
        } while (g < target);
    }
    __syncthreads();
}

// ---------------------------------------------------------------------------
// Persistent GRU. 128 CTAs x 512 thr. CTA owns 8 hidden units; W_hh slice in
// smem with row stride 28 (banks 28*ks+2*jp mod 32 near-bijective -> ~2 wf
// per W LDS.64).
// Thread = (half = w>>3 | bq = w&7 | ks = lane bits 2..4 | jp = lane bits 0..1):
//   8 batches b0=bq*8, unit pair j=j0+jp*2, K 1/16-split kofs = half*8+ks.
// Per k: 2 LDS.128(h, stride 68 conflict-free) + 8 pk2 + 3 LDS.64(W) + 24 FFMA2.
// Reduce: shfl over ks (xor 4,8,16), then cross-half via smem (Ht buf0).
// ---------------------------------------------------------------------------
#define HT_STRIDE 68
#define W_STRIDE 28
#define CHUNK_K 128
#define NCHUNK 8
#define WS_F (1024 * W_STRIDE)
#define HT_F (2 * CHUNK_K * HT_STRIDE)
#define SMEMB ((WS_F + HT_F) * 4)

__global__ __launch_bounds__(512) void gru_persist(const float* __restrict__ Whh,
                                                   const float* __restrict__ bhh)
{
    extern __shared__ float sm[];
    float* Ws = sm;              // [k][g*8 + u], row stride 28 (24 used)
    float* Ht = sm + WS_F;       // [buf][k][68]

    const int tid = threadIdx.x;
    const int w = tid >> 5, half = w >> 3, bq = w & 7;
    const int lane = tid & 31, ks = (lane >> 2) & 7, jp = lane & 3;
    const int b0 = bq * 8;
    const int j0 = blockIdx.x * 8, j = j0 + jp * 2;
    const int kofs = half * 8 + ks;          // 0..15

    for (int i = tid; i < 1024 * 6; i += 512) {
        int k = i / 6, q = i - k * 6, g = q >> 1, part = q & 1;
        *(float4*)&Ws[k * W_STRIDE + g * 8 + part * 4] =
            *(const float4*)(Whh + (size_t)k * Gg + g * Hh + j0 + part * 4);
    }
    const float2 br = *(const float2*)(bhh + j);
    const float2 bz = *(const float2*)(bhh + Hh + j);
    const float2 bn = *(const float2*)(bhh + 2 * Hh + j);
    __syncthreads();

    u64* red = (u64*)Ht;   // cross-half scratch; buf0 dead after c=7 entry sync

    for (int t = 0; t < Tt; ++t) {
        const float* hprev = g_h + (size_t)t * (Hh * Bb);
        float* hout       = g_h + (size_t)(t + 1) * (Hh * Bb);

        auto load_chunk = [&](int c, int buf) {
            const float* src = hprev + c * (CHUNK_K * Bb);
            float* dstb = Ht + buf * (CHUNK_K * HT_STRIDE);
            #pragma unroll
            for (int i = 0; i < 4; i++) {
                int f4 = i * 512 + tid;
                int row = f4 >> 4, q = f4 & 15;
                cp16(dstb + row * HT_STRIDE + q * 4, src + f4 * 4);
            }
            asm volatile("cp.async.commit_group;");
        };
        load_chunk(0, 0);

        u64 acc[3][8];
        #pragma unroll
        for (int g = 0; g < 3; g++)
            #pragma unroll
            for (int b = 0; b < 8; b++) acc[g][b] = 0ull;

        for (int c = 0; c < NCHUNK; ++c) {
            if (c < NCHUNK - 1) {
                load_chunk(c + 1, (c + 1) & 1);
                asm volatile("cp.async.wait_group 1;");
            } else {
                asm volatile("cp.async.wait_group 0;");
            }
            __syncthreads();
            const float* hb = Ht + (c & 1) * (CHUNK_K * HT_STRIDE)
                              + kofs * HT_STRIDE + b0;
            const float* wp = Ws + (c * CHUNK_K + kofs) * W_STRIDE + jp * 2;
            #pragma unroll 2
            for (int kk = 0; kk < 8; ++kk) {
                const float* hq = hb + kk * (16 * HT_STRIDE);
                float4 ha = *(const float4*)hq;
                float4 hbv = *(const float4*)(hq + 4);
                u64 hd0 = pk2(ha.x, ha.x),  hd1 = pk2(ha.y, ha.y);
                u64 hd2 = pk2(ha.z, ha.z),  hd3 = pk2(ha.w, ha.w);
                u64 hd4 = pk2(hbv.x, hbv.x), hd5 = pk2(hbv.y, hbv.y);
                u64 hd6 = pk2(hbv.z, hbv.z), hd7 = pk2(hbv.w, hbv.w);
                const float* wq = wp + kk * (16 * W_STRIDE);
                u64 wr = *(const u64*)(wq);
                u64 wz = *(const u64*)(wq + 8);
                u64 wn = *(const u64*)(wq + 16);
                f2(acc[0][0], hd0, wr); f2(acc[0][1], hd1, wr);
                f2(acc[0][2], hd2, wr); f2(acc[0][3], hd3, wr);
                f2(acc[0][4], hd4, wr); f2(acc[0][5], hd5, wr);
                f2(acc[0][6], hd6, wr); f2(acc[0][7], hd7, wr);
                f2(acc[1][0], hd0, wz); f2(acc[1][1], hd1, wz);
                f2(acc[1][2], hd2, wz); f2(acc[1][3], hd3, wz);
                f2(acc[1][4], hd4, wz); f2(acc[1][5], hd5, wz);
                f2(acc[1][6], hd6, wz); f2(acc[1][7], hd7, wz);
                f2(acc[2][0], hd0, wn); f2(acc[2][1], hd1, wn);
                f2(acc[2][2], hd2, wn); f2(acc[2][3], hd3, wn);
                f2(acc[2][4], hd4, wn); f2(acc[2][5], hd5, wn);
                f2(acc[2][6], hd6, wn); f2(acc[2][7], hd7, wn);
            }
            __syncthreads();
        }

        // issue epilogue global loads early (overlap the reduction)
        float2 gir[8], giz[8], gin[8];
        float hpj[8], hpj1[8];
        if (half == 0 && ks == 0) {
            const float* gp = g_gi + (size_t)t * (Bb * Gg);
            #pragma unroll
            for (int b = 0; b < 8; b++) {
                const float* gpb = gp + (size_t)(b0 + b) * Gg;
                gir[b] = *(const float2*)(gpb + j);
                giz[b] = *(const float2*)(gpb + Hh + j);
                gin[b] = *(const float2*)(gpb + 2 * Hh + j);
            }
            *(float4*)&hpj[0]  = *(const float4*)(hprev + (size_t)j * Bb + b0);
            *(float4*)&hpj[4]  = *(const float4*)(hprev + (size_t)j * Bb + b0 + 4);
            *(float4*)&hpj1[0] = *(const float4*)(hprev + (size_t)(j + 1) * Bb + b0);
            *(float4*)&hpj1[4] = *(const float4*)(hprev + (size_t)(j + 1) * Bb + b0 + 4);
        }

        // reduce over ks (lane bits 2..4)
        #pragma unroll
        for (int g = 0; g < 3; g++)
            #pragma unroll
            for (int b = 0; b < 8; b++) {
                u64 v = acc[g][b];
                v = add2(v, __shfl_xor_sync(0xffffffffu, v, 4));
                v = add2(v, __shfl_xor_sync(0xffffffffu, v, 8));
                v = add2(v, __shfl_xor_sync(0xffffffffu, v, 16));
                acc[g][b] = v;
            }
        // cross-half: half1 ks0 lanes publish partials (buf0 region is dead)
        if (half == 1 && ks == 0) {
            u64* rs = red + (size_t)(bq * 4 + jp) * 24;
            #pragma unroll
            for (int g = 0; g < 3; g++)
                #pragma unroll
                for (int b = 0; b < 8; b++) rs[g * 8 + b] = acc[g][b];
        }
        __syncthreads();

        if (half == 0 && ks == 0) {
            const u64* rs = red + (size_t)(bq * 4 + jp) * 24;
            float hj[8], hj1[8];
            #pragma unroll
            for (int b = 0; b < 8; b++) {
                float2 sr = up2(add2(acc[0][b], rs[b]));
                float2 sz = up2(add2(acc[1][b], rs[8 + b]));
                float2 sn = up2(add2(acc[2][b], rs[16 + b]));
                float r0 = sigm(gir[b].x + sr.x + br.x);
                float r1 = sigm(gir[b].y + sr.y + br.y);
                float z0 = sigm(giz[b].x + sz.x + bz.x);
                float z1 = sigm(giz[b].y + sz.y + bz.y);
                float n0 = tanhf(gin[b].x + r0 * (sn.x + bn.x));
                float n1 = tanhf(gin[b].y + r1 * (sn.y + bn.y));
                hj[b]  = (1.0f - z0) * n0 + z0 * hpj[b];
                hj1[b] = (1.0f - z1) * n1 + z1 * hpj1[b];
            }
            *(float4*)(hout + (size_t)j * Bb + b0)           = *(float4*)&hj[0];
            *(float4*)(hout + (size_t)j * Bb + b0 + 4)       = *(float4*)&hj[4];
            *(float4*)(hout + (size_t)(j + 1) * Bb + b0)     = *(float4*)&hj1[0];
            *(float4*)(hout + (size_t)(j + 1) * Bb + b0 + 4) = *(float4*)&hj1[4];
        }
        grid_bar((unsigned)(t + 1));
    }
}

extern "C" void kernel_launch(void* const* d_in, const int* in_sizes, int n_in,
                              void* d_out, int out_size)
{
    const float* X    = (const float*)d_in[0];
    const float* init = (const float*)d_in[1];
    const float* Wih  = (const float*)d_in[2];
    const float* Whh  = (const float*)d_in[3];
    const float* bih  = (const float*)d_in[4];
    const float* bhh  = (const float*)d_in[5];
    const float* Wout = (const float*)d_in[6];
    const float* bout = (const float*)d_in[7];
    float* out = (float*)d_out;

    cudaFuncSetAttribute(gru_persist,
                         cudaFuncAttributeMaxDynamicSharedMemorySize, SMEMB);

    init_bar<<<1, 1>>>();
    h0_init<<<256, 256>>>(init);

    // Phase 1: gi = X @ W_ih + b_ih   (M=65536, N=3072, K=512)
    sgemm<512, 0><<<dim3(Gg / 64, (Bb * Tt) / 128), 256>>>(X, Wih, bih, nullptr);

    // Phase 2: all 1024 GRU steps in one persistent kernel
    gru_persist<<<NCTA, 512, SMEMB>>>(Whh, bhh);

    // Phase 3: out = h @ W_out + b_out  (M=65536, N=256, K=1024)
    sgemm<1024, 1><<<dim3(Oo / 64, (Bb * Tt) / 128), 256>>>(nullptr, Wout, bout, out);
}

// round 10
// speedup vs baseline: 1.1340x; 1.1340x over previous
#include <cuda_runtime.h>
#include <cstdint>

#define Tt 1024
#define Bb 64
#define Ii 512
#define Hh 1024
#define Gg 3072
#define Oo 256
#define NCTA 128

// scratch (device globals = allowed scratch)
__device__ float g_gi[(size_t)Tt * Bb * Gg];        // [t][b][g]
__device__ float g_h [(size_t)(Tt + 1) * Hh * Bb];  // [t][k][b], slot 0 = init^T
__device__ unsigned g_bar_count;

typedef unsigned long long u64;

__device__ __forceinline__ u64 pk2(float x, float y) {
    u64 r; asm("mov.b64 %0,{%1,%2};" : "=l"(r) : "f"(x), "f"(y)); return r;
}
__device__ __forceinline__ void f2(u64& d, u64 a, u64 b) {
    asm("fma.rn.f32x2 %0,%1,%2,%0;" : "+l"(d) : "l"(a), "l"(b));
}
__device__ __forceinline__ u64 add2(u64 a, u64 b) {
    u64 d; asm("add.rn.f32x2 %0,%1,%2;" : "=l"(d) : "l"(a), "l"(b)); return d;
}
__device__ __forceinline__ float2 up2(u64 a) {
    float2 f; asm("mov.b64 {%0,%1},%2;" : "=f"(f.x), "=f"(f.y) : "l"(a)); return f;
}
__device__ __forceinline__ float sigm(float x) { return 1.0f / (1.0f + __expf(-x)); }

__device__ __forceinline__ void cp16(void* smem, const void* g) {
    uint32_t s = (uint32_t)__cvta_generic_to_shared(smem);
    asm volatile("cp.async.cg.shared.global [%0], [%1], 16;" :: "r"(s), "l"(g));
}

__global__ void init_bar() { g_bar_count = 0u; }

// transpose init [b][k] -> g_h slot 0 [k][b]
__global__ void h0_init(const float* __restrict__ init) {
    int i = blockIdx.x * 256 + threadIdx.x;   // 65536
    int k = i >> 6, b = i & 63;
    g_h[(size_t)k * Bb + b] = init[(size_t)b * Hh + k];
}

// ---------------------------------------------------------------------------
// SGEMM: C[M,N] = A[M,K] @ W[K,N] + bias.  BM=128, BN=64, BK=16, 256 threads,
// thread-tile 8m x 4n (n packed as f32x2 pairs).
// MODE 0: A=X [M=b*1024+t, K=512], W_ih ldw=3072, writes g_gi[t][b][g].
// MODE 1: A=g_h transposed [t][k][b] (m=t*64+b), K=1024, ldw=256, writes out.
// ---------------------------------------------------------------------------
template <int K, int MODE>
__global__ __launch_bounds__(256) void sgemm(const float* __restrict__ Ain,
                                             const float* __restrict__ W,
                                             const float* __restrict__ bias,
                                             float* __restrict__ Cout)
{
    __shared__ float As[16][132];
    __shared__ float Bs[16][64];
    const int ldw = (MODE == 0) ? Gg : Oo;
    const int m0 = blockIdx.y * 128, n0 = blockIdx.x * 64;
    const int tid = threadIdx.x;
    const int tn = tid & 15, tm = tid >> 4;

    u64 acc[8][2];
    #pragma unroll
    for (int m = 0; m < 8; m++) { acc[m][0] = 0ull; acc[m][1] = 0ull; }

    for (int k0 = 0; k0 < K; k0 += 16) {
        if (MODE == 0) {
            #pragma unroll
            for (int i = 0; i < 2; i++) {
                int idx = tid + i * 256;            // 512 float4 = 128 rows x 4
                int r = idx >> 2, kq = idx & 3;
                float4 v = *(const float4*)(Ain + (size_t)(m0 + r) * K + k0 + kq * 4);
                As[kq * 4 + 0][r] = v.x; As[kq * 4 + 1][r] = v.y;
                As[kq * 4 + 2][r] = v.z; As[kq * 4 + 3][r] = v.w;
            }
        } else {
            // tile = 2 t-slices x 16 k x 64 b from g_h[t+1][k][b]
            #pragma unroll
            for (int i = 0; i < 2; i++) {
                int idx = tid + i * 256;            // 512 float4
                int tsl = idx >> 8, k = (idx >> 4) & 15, q = idx & 15;
                float4 v = *(const float4*)(g_h +
                    (size_t)((m0 >> 6) + tsl + 1) * (Hh * Bb) + (size_t)(k0 + k) * Bb + q * 4);
                *(float4*)&As[k][tsl * 64 + q * 4] = v;
            }
        }
        {
            int r = tid >> 4, gq = tid & 15;        // 16 rows x 16 float4
            *(float4*)&Bs[r][gq * 4] =
                *(const float4*)(W + (size_t)(k0 + r) * ldw + n0 + gq * 4);
        }
        __syncthreads();
        #pragma unroll
        for (int k = 0; k < 16; k++) {
            float4 a0 = *(float4*)&As[k][tm * 8];
            float4 a1 = *(float4*)&As[k][tm * 8 + 4];
            u64 b0 = *(u64*)&Bs[k][tn * 4];
            u64 b1 = *(u64*)&Bs[k][tn * 4 + 2];
            float av[8] = {a0.x, a0.y, a0.z, a0.w, a1.x, a1.y, a1.z, a1.w};
            #pragma unroll
            for (int m = 0; m < 8; m++) {
                u64 ad = pk2(av[m], av[m]);
                f2(acc[m][0], ad, b0);
                f2(acc[m][1], ad, b1);
            }
        }
        __syncthreads();
    }

    const int n = n0 + tn * 4;
    float4 bi = *(const float4*)(bias + n);
    #pragma unroll
    for (int m = 0; m < 8; m++) {
        int r = m0 + tm * 8 + m;
        float2 p0 = up2(acc[m][0]), p1 = up2(acc[m][1]);
        float4 o = make_float4(p0.x + bi.x, p0.y + bi.y, p1.x + bi.z, p1.y + bi.w);
        if (MODE == 0) {
            int b = r >> 10, t = r & 1023;
            *(float4*)(g_gi + ((size_t)t * Bb + b) * Gg + n) = o;
        } else {
            int t = r >> 6, b = r & 63;
            *(float4*)(Cout + ((size_t)b * Tt + t) * Oo + n) = o;
        }
    }
}

// ---------------------------------------------------------------------------
// Grid barrier: monotonic arrival counter, target = (t+1)*NCTA.
// ---------------------------------------------------------------------------
__device__ __forceinline__ void grid_bar(unsigned t1) {
    __syncthreads();
    if (threadIdx.x == 0) {
        unsigned* pc = &g_bar_count;
        asm volatile("red.add.release.gpu.u32 [%0],1;" :: "l"(pc) : "memory");
        const unsigned target = t1 * NCTA;
        unsigned g;
        do {
            asm volatile("ld.acquire.gpu.u32 %0,[%1];" : "=r"(g) : "l"(pc) : "memory");
        } while (g < target);
    }
    __syncthreads();
}

// ---------------------------------------------------------------------------
// Persistent GRU. 128 CTAs x 256 thr (8 warps). CTA owns 8 hidden units; W_hh
// slice (1024 x 24 f = 96 KB) in smem all steps.
// Thread = (bq = warp id -> b0 = bq*8 | ks = lane bits 2..4 | jp = lane bits
// 0..1): 8 batches, unit pair j = j0 + jp*2, K 1/8-split (k = kk*8 + ks).
// Per warp-kk: 2 LDS.128 (h, stride 68: banks 4k+q tile perfectly, 2 wf)
//            + 3 LDS.64 (W, stride 24, degree-2 floor, 6 wf)
//            + 8 pk2 + 24 FFMA2  -> crossbar 8.2K cyc/step < FMA 12.3K: FMA-bound.
// Reduce: 3x shfl.bfly over ks. ~100 regs at 256 thr (no 128 cap, no spills).
// ---------------------------------------------------------------------------
#define HT_STRIDE 68
#define W_STRIDE 24
#define CHUNK_K 128
#define NCHUNK 8
#define WS_F (1024 * W_STRIDE)
#define HT_F (2 * CHUNK_K * HT_STRIDE)
#define SMEMB ((WS_F + HT_F) * 4)

__global__ __launch_bounds__(256) void gru_persist(const float* __restrict__ Whh,
                                                   const float* __restrict__ bhh)
{
    extern __shared__ float sm[];
    float* Ws = sm;              // [k][g*8 + u], 1024 x 24
    float* Ht = sm + WS_F;       // [buf][k][68]

    const int tid = threadIdx.x;
    const int bq = tid >> 5;                 // warp id = batch octet
    const int lane = tid & 31, ks = (lane >> 2) & 7, jp = lane & 3;
    const int b0 = bq * 8;
    const int j0 = blockIdx.x * 8, j = j0 + jp * 2;

    for (int i = tid; i < 1024 * 6; i += 256) {
        int k = i / 6, q = i - k * 6, g = q >> 1, part = q & 1;
        *(float4*)&Ws[k * W_STRIDE + g * 8 + part * 4] =
            *(const float4*)(Whh + (size_t)k * Gg + g * Hh + j0 + part * 4);
    }
    const float2 br = *(const float2*)(bhh + j);
    const float2 bz = *(const float2*)(bhh + Hh + j);
    const float2 bn = *(const float2*)(bhh + 2 * Hh + j);
    __syncthreads();

    for (int t = 0; t < Tt; ++t) {
        const float* hprev = g_h + (size_t)t * (Hh * Bb);
        float* hout       = g_h + (size_t)(t + 1) * (Hh * Bb);

        // chunk = 128 k x 64 b = 2048 float4; dst rows padded to 68 floats.
        auto load_chunk = [&](int c, int buf) {
            const float* src = hprev + c * (CHUNK_K * Bb);
            float* dstb = Ht + buf * (CHUNK_K * HT_STRIDE);
            #pragma unroll
            for (int i = 0; i < 8; i++) {
                int f4 = i * 256 + tid;
                int row = f4 >> 4, q = f4 & 15;
                cp16(dstb + row * HT_STRIDE + q * 4, src + f4 * 4);
            }
            asm volatile("cp.async.commit_group;");
        };
        load_chunk(0, 0);

        u64 acc[3][8];
        #pragma unroll
        for (int g = 0; g < 3; g++)
            #pragma unroll
            for (int b = 0; b < 8; b++) acc[g][b] = 0ull;

        for (int c = 0; c < NCHUNK; ++c) {
            if (c < NCHUNK - 1) {
                load_chunk(c + 1, (c + 1) & 1);
                asm volatile("cp.async.wait_group 1;");
            } else {
                asm volatile("cp.async.wait_group 0;");
            }
            __syncthreads();
            const float* hb = Ht + (c & 1) * (CHUNK_K * HT_STRIDE)
                              + ks * HT_STRIDE + b0;
            const float* wp = Ws + (c * CHUNK_K + ks) * W_STRIDE + jp * 2;
            #pragma unroll 4
            for (int kk = 0; kk < 16; ++kk) {
                const float* hq = hb + kk * (8 * HT_STRIDE);
                float4 ha = *(const float4*)hq;
                float4 hc = *(const float4*)(hq + 4);
                u64 hd0 = pk2(ha.x, ha.x), hd1 = pk2(ha.y, ha.y);
                u64 hd2 = pk2(ha.z, ha.z), hd3 = pk2(ha.w, ha.w);
                u64 hd4 = pk2(hc.x, hc.x), hd5 = pk2(hc.y, hc.y);
                u64 hd6 = pk2(hc.z, hc.z), hd7 = pk2(hc.w, hc.w);
                const float* wq = wp + kk * (8 * W_STRIDE);
                u64 wr = *(const u64*)(wq);
                u64 wz = *(const u64*)(wq + 8);
                u64 wn = *(const u64*)(wq + 16);
                f2(acc[0][0], hd0, wr); f2(acc[0][1], hd1, wr);
                f2(acc[0][2], hd2, wr); f2(acc[0][3], hd3, wr);
                f2(acc[0][4], hd4, wr); f2(acc[0][5], hd5, wr);
                f2(acc[0][6], hd6, wr); f2(acc[0][7], hd7, wr);
                f2(acc[1][0], hd0, wz); f2(acc[1][1], hd1, wz);
                f2(acc[1][2], hd2, wz); f2(acc[1][3], hd3, wz);
                f2(acc[1][4], hd4, wz); f2(acc[1][5], hd5, wz);
                f2(acc[1][6], hd6, wz); f2(acc[1][7], hd7, wz);
                f2(acc[2][0], hd0, wn); f2(acc[2][1], hd1, wn);
                f2(acc[2][2], hd2, wn); f2(acc[2][3], hd3, wn);
                f2(acc[2][4], hd4, wn); f2(acc[2][5], hd5, wn);
                f2(acc[2][6], hd6, wn); f2(acc[2][7], hd7, wn);
            }
            __syncthreads();
        }

        // epilogue global loads first (overlap the shfl reduction)
        float2 gir[8], giz[8], gin[8];
        float hpj[8], hpj1[8];
        if (ks == 0) {
            const float* gp = g_gi + (size_t)t * (Bb * Gg);
            #pragma unroll
            for (int b = 0; b < 8; b++) {
                const float* gpb = gp + (size_t)(b0 + b) * Gg;
                gir[b] = *(const float2*)(gpb + j);
                giz[b] = *(const float2*)(gpb + Hh + j);
                gin[b] = *(const float2*)(gpb + 2 * Hh + j);
            }
            *(float4*)&hpj[0]  = *(const float4*)(hprev + (size_t)j * Bb + b0);
            *(float4*)&hpj[4]  = *(const float4*)(hprev + (size_t)j * Bb + b0 + 4);
            *(float4*)&hpj1[0] = *(const float4*)(hprev + (size_t)(j + 1) * Bb + b0);
            *(float4*)&hpj1[4] = *(const float4*)(hprev + (size_t)(j + 1) * Bb + b0 + 4);
        }

        // reduce over ks (lane bits 2..4)
        #pragma unroll
        for (int g = 0; g < 3; g++)
            #pragma unroll
            for (int b = 0; b < 8; b++) {
                u64 v = acc[g][b];
                v = add2(v, __shfl_xor_sync(0xffffffffu, v, 4));
                v = add2(v, __shfl_xor_sync(0xffffffffu, v, 8));
                v = add2(v, __shfl_xor_sync(0xffffffffu, v, 16));
                acc[g][b] = v;
            }

        if (ks == 0) {
            float hj[8], hj1[8];
            #pragma unroll
            for (int b = 0; b < 8; b++) {
                float2 sr = up2(acc[0][b]), sz = up2(acc[1][b]), sn = up2(acc[2][b]);
                float r0 = sigm(gir[b].x + sr.x + br.x);
                float r1 = sigm(gir[b].y + sr.y + br.y);
                float z0 = sigm(giz[b].x + sz.x + bz.x);
                float z1 = sigm(giz[b].y + sz.y + bz.y);
                float n0 = tanhf(gin[b].x + r0 * (sn.x + bn.x));
                float n1 = tanhf(gin[b].y + r1 * (sn.y + bn.y));
                hj[b]  = (1.0f - z0) * n0 + z0 * hpj[b];
                hj1[b] = (1.0f - z1) * n1 + z1 * hpj1[b];
            }
            *(float4*)(hout + (size_t)j * Bb + b0)           = *(float4*)&hj[0];
            *(float4*)(hout + (size_t)j * Bb + b0 + 4)       = *(float4*)&hj[4];
            *(float4*)(hout + (size_t)(j + 1) * Bb + b0)     = *(float4*)&hj1[0];
            *(float4*)(hout + (size_t)(j + 1) * Bb + b0 + 4) = *(float4*)&hj1[4];
        }
        grid_bar((unsigned)(t + 1));
    }
}

extern "C" void kernel_launch(void* const* d_in, const int* in_sizes, int n_in,
                              void* d_out, int out_size)
{
    const float* X    = (const float*)d_in[0];
    const float* init = (const float*)d_in[1];
    const float* Wih  = (const float*)d_in[2];
    const float* Whh  = (const float*)d_in[3];
    const float* bih  = (const float*)d_in[4];
    const float* bhh  = (const float*)d_in[5];
    const float* Wout = (const float*)d_in[6];
    const float* bout = (const float*)d_in[7];
    float* out = (float*)d_out;

    cudaFuncSetAttribute(gru_persist,
                         cudaFuncAttributeMaxDynamicSharedMemorySize, SMEMB);

    init_bar<<<1, 1>>>();
    h0_init<<<256, 256>>>(init);

    // Phase 1: gi = X @ W_ih + b_ih   (M=65536, N=3072, K=512)
    sgemm<512, 0><<<dim3(Gg / 64, (Bb * Tt) / 128), 256>>>(X, Wih, bih, nullptr);

    // Phase 2: all 1024 GRU steps in one persistent kernel
    gru_persist<<<NCTA, 256, SMEMB>>>(Whh, bhh);

    // Phase 3: out = h @ W_out + b_out  (M=65536, N=256, K=1024)
    sgemm<1024, 1><<<dim3(Oo / 64, (Bb * Tt) / 128), 256>>>(nullptr, Wout, bout, out);
}